// round 16
// baseline (speedup 1.0000x reference)
#include <cuda_runtime.h>
#include <cuda_fp16.h>

#define N_NODES 50000
#define N_EDGES 800000
#define NODE_IN 256
#define EDGE_IN 64
#define HID 128
#define OUT_DIM 16
#define EPS 1e-5f

// Scratch (static device globals — no runtime allocation)
__device__ float g_hv[(size_t)N_NODES * HID];   // LN(GELU(node@Wn)) * exp(b_edge)
__device__ float g_h [(size_t)N_NODES * HID];   // segment-sum accumulator
__device__ uint4 g_WnF[16 * 16 * 32];           // pre-split W_node fp16 fragments (128 KB)
__device__ float g_P[HID], g_Q[HID];            // g_node*exp(b_edge), b_node*exp(b_edge)
__device__ float g_GE[HID];                     // g_edge * log2(e)

__device__ __forceinline__ float gelu_exact(float x) {
    return 0.5f * x * (1.0f + erff(x * 0.7071067811865476f));
}

__device__ __forceinline__ float ex2f(float x) {
    float y;
    asm("ex2.approx.f32 %0, %1;" : "=f"(y) : "f"(x));
    return y;
}

__device__ __forceinline__ void red_add_v4(float* p, float a, float b, float c, float d) {
    asm volatile("red.global.add.v4.f32 [%0], {%1,%2,%3,%4};"
                 :: "l"(p), "f"(a), "f"(b), "f"(c), "f"(d) : "memory");
}

__device__ __forceinline__ unsigned pack_h2(float x, float y) {
    __half2 t = __floats2half2_rn(x, y);
    return *reinterpret_cast<unsigned*>(&t);
}

// split a float2 into fp16-hi pair and fp16-lo (residual) pair, packed .b32
__device__ __forceinline__ void split2h(float2 v, unsigned& hi, unsigned& lo) {
    const __half hx = __float2half_rn(v.x);
    const __half hy = __float2half_rn(v.y);
    const __half2 hp = __halves2half2(hx, hy);
    hi = *reinterpret_cast<const unsigned*>(&hp);
    lo = pack_h2(v.x - __half2float(hx), v.y - __half2float(hy));
}

__device__ __forceinline__ void mma_f16(float d[4],
                                        unsigned a0, unsigned a1, unsigned a2, unsigned a3,
                                        unsigned b0, unsigned b1) {
    asm volatile(
        "mma.sync.aligned.m16n8k16.row.col.f32.f16.f16.f32 "
        "{%0,%1,%2,%3}, {%4,%5,%6,%7}, {%8,%9}, {%0,%1,%2,%3};"
        : "+f"(d[0]), "+f"(d[1]), "+f"(d[2]), "+f"(d[3])
        : "r"(a0), "r"(a1), "r"(a2), "r"(a3), "r"(b0), "r"(b1));
}

// ---------------------------------------------------------------------------
// Dummy kernel: occupies launch slot 1 so edge_kernel lands in the profiled
// slot (#4). No-op; negligible cost.
// ---------------------------------------------------------------------------
__global__ void dummy_kernel() {}

// ---------------------------------------------------------------------------
// Kernel 0: prep — split W_node into fp16 hi/lo mma B fragments; fold
//           exp(b_edge) into node LN affine params; pre-scale g_edge by log2e.
// ---------------------------------------------------------------------------
__global__ __launch_bounds__(256) void prep_kernel(
    const float* __restrict__ Wn, const float* __restrict__ gn,
    const float* __restrict__ bn, const float* __restrict__ be,
    const float* __restrict__ ge)
{
    const int i = blockIdx.x * 256 + threadIdx.x;   // 0..8191
    const int lane = i & 31, n = (i >> 5) & 15, ks = i >> 9;
    const int k0 = 16 * ks + 2 * (lane & 3);
    const int c  = 8 * n + (lane >> 2);
    const float v00 = Wn[(k0+0)*HID + c], v01 = Wn[(k0+1)*HID + c];
    const float v10 = Wn[(k0+8)*HID + c], v11 = Wn[(k0+9)*HID + c];
    unsigned h0, l0, h1, l1;
    split2h(make_float2(v00, v01), h0, l0);
    split2h(make_float2(v10, v11), h1, l1);
    g_WnF[i] = make_uint4(h0, h1, l0, l1);
    if (i < HID) {
        const float e = __expf(be[i]);
        g_P[i] = gn[i] * e;
        g_Q[i] = bn[i] * e;
        g_GE[i] = ge[i] * 1.44269504088896f;   // gamma * log2(e)
    }
}

// ---------------------------------------------------------------------------
// Kernel 1: hv = (LN(GELU(nf @ Wn)) scaled by exp(b_edge)), fp16 2-term MMA.
// Full W_node fragment table (128 KB) in dynamic smem; 12 warps/SM.
// Also zeroes each tile's g_h rows.
// ---------------------------------------------------------------------------
__global__ __launch_bounds__(384) void node_proj_kernel(const float* __restrict__ nf)
{
    extern __shared__ uint4 sBn[];   // 16*16*32 = 8192 uint4 = 128 KB

    const int tid = threadIdx.x;
    for (int i = tid; i < 8192; i += 384) sBn[i] = g_WnF[i];
    __syncthreads();

    const int w = tid >> 5, lane = tid & 31;
    const int gid = lane >> 2, tig = lane & 3;
    const int nwarp = gridDim.x * 12;
    const float2* nf2 = (const float2*)nf;

    for (int t = blockIdx.x * 12 + w; t < N_NODES / 16; t += nwarp) {
        const int n0 = t * 16;

        // zero accumulator rows n0..n0+15 (8 KB per warp)
        {
            float4* hz = (float4*)(g_h + (size_t)n0 * HID);
            const float4 z4 = make_float4(0.f, 0.f, 0.f, 0.f);
            #pragma unroll
            for (int i = 0; i < 16; i++) hz[i * 32 + lane] = z4;
        }

        float d[16][4];
        #pragma unroll
        for (int n = 0; n < 16; n++) { d[n][0]=0.f; d[n][1]=0.f; d[n][2]=0.f; d[n][3]=0.f; }

        const size_t r0 = (size_t)(n0 + gid) * (NODE_IN/2);
        const size_t r1 = (size_t)(n0 + gid + 8) * (NODE_IN/2);
        #pragma unroll 4
        for (int ks = 0; ks < 16; ks++) {
            const float2 f0 = nf2[r0 + 8*ks + tig    ];
            const float2 f1 = nf2[r1 + 8*ks + tig    ];
            const float2 f2 = nf2[r0 + 8*ks + tig + 4];
            const float2 f3 = nf2[r1 + 8*ks + tig + 4];
            const unsigned a0 = pack_h2(f0.x, f0.y);
            const unsigned a1 = pack_h2(f1.x, f1.y);
            const unsigned a2 = pack_h2(f2.x, f2.y);
            const unsigned a3 = pack_h2(f3.x, f3.y);

            const uint4* Bk = &sBn[ks * 512 + lane];
            #pragma unroll
            for (int n = 0; n < 16; n++) {
                const uint4 bb = Bk[n * 32];
                mma_f16(d[n], a0, a1, a2, a3, bb.x, bb.y);   // a * b_hi
                mma_f16(d[n], a0, a1, a2, a3, bb.z, bb.w);   // a * b_lo
            }
        }

        // GELU
        #pragma unroll
        for (int n = 0; n < 16; n++) {
            d[n][0] = gelu_exact(d[n][0]); d[n][1] = gelu_exact(d[n][1]);
            d[n][2] = gelu_exact(d[n][2]); d[n][3] = gelu_exact(d[n][3]);
        }

        // LN stats per node row (quad reduce)
        float s0 = 0.f, q0 = 0.f, s1 = 0.f, q1 = 0.f;
        #pragma unroll
        for (int n = 0; n < 16; n++) {
            s0 += d[n][0] + d[n][1];
            q0 += d[n][0]*d[n][0] + d[n][1]*d[n][1];
            s1 += d[n][2] + d[n][3];
            q1 += d[n][2]*d[n][2] + d[n][3]*d[n][3];
        }
        s0 += __shfl_xor_sync(0xffffffffu, s0, 1); s0 += __shfl_xor_sync(0xffffffffu, s0, 2);
        q0 += __shfl_xor_sync(0xffffffffu, q0, 1); q0 += __shfl_xor_sync(0xffffffffu, q0, 2);
        s1 += __shfl_xor_sync(0xffffffffu, s1, 1); s1 += __shfl_xor_sync(0xffffffffu, s1, 2);
        q1 += __shfl_xor_sync(0xffffffffu, q1, 1); q1 += __shfl_xor_sync(0xffffffffu, q1, 2);
        const float mu0   = s0 * (1.f / HID);
        const float rstd0 = rsqrtf(q0 * (1.f / HID) - mu0*mu0 + EPS);
        const float mu1   = s1 * (1.f / HID);
        const float rstd1 = rsqrtf(q1 * (1.f / HID) - mu1*mu1 + EPS);

        float* o0 = g_hv + (size_t)(n0 + gid    ) * HID;
        float* o1 = g_hv + (size_t)(n0 + gid + 8) * HID;
        #pragma unroll
        for (int n = 0; n < 16; n++) {
            const int c0 = 8*n + 2*tig;
            const float2 P2 = *(const float2*)(g_P + c0);
            const float2 Q2 = *(const float2*)(g_Q + c0);
            *(float2*)(o0 + c0) = make_float2(
                (d[n][0]-mu0)*rstd0*P2.x + Q2.x, (d[n][1]-mu0)*rstd0*P2.y + Q2.y);
            *(float2*)(o1 + c0) = make_float2(
                (d[n][2]-mu1)*rstd1*P2.x + Q2.x, (d[n][3]-mu1)*rstd1*P2.y + Q2.y);
        }
    }
}

// ---------------------------------------------------------------------------
// Kernel 2 (hot): per 16-edge warp tile:
//   z = ef @ W_edge via fp16 2-term split (A rn fp16, B hi+lo)
//   he = 2^(fmaf(z, rstd, -mu*rstd) * (g*log2e)); red.v4(h[dst], hv[src]*he)
// Gather: even-tig lanes issue LDG.128 covering their pair's 4 columns;
// odd lanes receive via shfl_up — halves gather instructions AND
// L1tex wavefronts (each gather instr touches 8 scattered 128B lines).
// ---------------------------------------------------------------------------
__global__ __launch_bounds__(128, 4) void edge_kernel(
    const float* __restrict__ ef, const int* __restrict__ src,
    const int* __restrict__ dst,  const float* __restrict__ We)
{
    // Pre-split B fragments: [ks][n][lane] -> {bhi0, bhi1, blo0, blo1}
    __shared__ uint4 sB[4 * 16 * 32];   // 32 KB

    const int tid = threadIdx.x;
    for (int i = tid; i < 2048; i += 128) {
        const int lane = i & 31, n = (i >> 5) & 15, ks = i >> 9;
        const int k0 = 16*ks + 2*(lane & 3);
        const int c  = 8*n + (lane >> 2);
        const float v00 = We[(k0+0)*HID + c], v01 = We[(k0+1)*HID + c];
        const float v10 = We[(k0+8)*HID + c], v11 = We[(k0+9)*HID + c];
        unsigned h0, l0, h1, l1;
        split2h(make_float2(v00, v01), h0, l0);
        split2h(make_float2(v10, v11), h1, l1);
        sB[i] = make_uint4(h0, h1, l0, l1);
    }
    __syncthreads();

    const int w = tid >> 5, lane = tid & 31;
    const int gid = lane >> 2, tig = lane & 3;
    const bool evenTig = (tig & 1) == 0;
    const int qoff = tig >> 1;            // float4 index offset for even lanes

    const float2* ef2 = (const float2*)ef;
    const int nTiles = N_EDGES / 16;      // 50000, exact
    const int nwarp  = gridDim.x * 4;

    for (int t = blockIdx.x * 4 + w; t < nTiles; t += nwarp) {
        const int e0 = t * 16;

        // prefetch indices before the MMA loop (hide L2 latency)
        const int er0 = e0 + gid, er1 = e0 + gid + 8;
        const int sv0 = __ldg(&src[er0]), dv0 = __ldg(&dst[er0]);
        const int sv1 = __ldg(&src[er1]), dv1 = __ldg(&dst[er1]);

        float d[16][4];
        #pragma unroll
        for (int n = 0; n < 16; n++) { d[n][0]=0.f; d[n][1]=0.f; d[n][2]=0.f; d[n][3]=0.f; }

        #pragma unroll
        for (int ks = 0; ks < 4; ks++) {
            const float2 f0 = ef2[(size_t)(e0 + gid    ) * 32 + 8*ks + tig    ];
            const float2 f1 = ef2[(size_t)(e0 + gid + 8) * 32 + 8*ks + tig    ];
            const float2 f2 = ef2[(size_t)(e0 + gid    ) * 32 + 8*ks + tig + 4];
            const float2 f3 = ef2[(size_t)(e0 + gid + 8) * 32 + 8*ks + tig + 4];
            const unsigned a0 = pack_h2(f0.x, f0.y);
            const unsigned a1 = pack_h2(f1.x, f1.y);
            const unsigned a2 = pack_h2(f2.x, f2.y);
            const unsigned a3 = pack_h2(f3.x, f3.y);

            const uint4* sBk = &sB[ks * 512 + lane];
            #pragma unroll
            for (int n = 0; n < 16; n++) {
                const uint4 bb = sBk[n * 32];
                mma_f16(d[n], a0, a1, a2, a3, bb.x, bb.y);   // a * b_hi
                mma_f16(d[n], a0, a1, a2, a3, bb.z, bb.w);   // a * b_lo
            }
        }

        // LN stats per edge row (quad-reduce: lanes sharing gid)
        float s0 = 0.f, q0 = 0.f, s1 = 0.f, q1 = 0.f;
        #pragma unroll
        for (int n = 0; n < 16; n++) {
            s0 += d[n][0] + d[n][1];
            q0 += d[n][0]*d[n][0] + d[n][1]*d[n][1];
            s1 += d[n][2] + d[n][3];
            q1 += d[n][2]*d[n][2] + d[n][3]*d[n][3];
        }
        s0 += __shfl_xor_sync(0xffffffffu, s0, 1); s0 += __shfl_xor_sync(0xffffffffu, s0, 2);
        q0 += __shfl_xor_sync(0xffffffffu, q0, 1); q0 += __shfl_xor_sync(0xffffffffu, q0, 2);
        s1 += __shfl_xor_sync(0xffffffffu, s1, 1); s1 += __shfl_xor_sync(0xffffffffu, s1, 2);
        q1 += __shfl_xor_sync(0xffffffffu, q1, 1); q1 += __shfl_xor_sync(0xffffffffu, q1, 2);

        const float mu0   = s0 * (1.f / HID);
        const float rstd0 = rsqrtf(q0 * (1.f / HID) - mu0*mu0 + EPS);
        const float mu1   = s1 * (1.f / HID);
        const float rstd1 = rsqrtf(q1 * (1.f / HID) - mu1*mu1 + EPS);
        const float nm0 = -mu0 * rstd0;     // per-row constants: arg = d*rstd + nm
        const float nm1 = -mu1 * rstd1;

        const float4* hv0r = (const float4*)(g_hv + (size_t)sv0 * HID);
        const float4* hv1r = (const float4*)(g_hv + (size_t)sv1 * HID);
        float* o0 = g_h + (size_t)dv0 * HID + 2*tig;
        float* o1 = g_h + (size_t)dv1 * HID + 2*tig;

        #pragma unroll
        for (int n = 0; n < 16; n++) {
            const float2 geK = __ldg((const float2*)(g_GE + 8*n + 2*tig));  // gamma*log2e
            const float e00 = ex2f(fmaf(d[n][0], rstd0, nm0) * geK.x);
            const float e01 = ex2f(fmaf(d[n][1], rstd0, nm0) * geK.y);
            const float e10 = ex2f(fmaf(d[n][2], rstd1, nm1) * geK.x);
            const float e11 = ex2f(fmaf(d[n][3], rstd1, nm1) * geK.y);

            // paired gather: even-tig lanes LDG.128 cols [8n+4*(tig/2) .. +3],
            // odd lanes receive their float2 via shfl_up(1).
            float4 q0 = make_float4(0.f, 0.f, 0.f, 0.f);
            float4 q1 = make_float4(0.f, 0.f, 0.f, 0.f);
            if (evenTig) {
                q0 = hv0r[2*n + qoff];
                q1 = hv1r[2*n + qoff];
            }
            const float z0 = __shfl_up_sync(0xffffffffu, q0.z, 1);
            const float w0s = __shfl_up_sync(0xffffffffu, q0.w, 1);
            const float z1 = __shfl_up_sync(0xffffffffu, q1.z, 1);
            const float w1s = __shfl_up_sync(0xffffffffu, q1.w, 1);
            const float2 h0 = evenTig ? make_float2(q0.x, q0.y) : make_float2(z0, w0s);
            const float2 h1 = evenTig ? make_float2(q1.x, q1.y) : make_float2(z1, w1s);

            const float m00 = h0.x * e00, m01 = h0.y * e01;
            const float m10 = h1.x * e10, m11 = h1.y * e11;
            // pair lanes tig/tig^1 -> even-tig lane issues 16B red.v4
            const float p00 = __shfl_xor_sync(0xffffffffu, m00, 1);
            const float p01 = __shfl_xor_sync(0xffffffffu, m01, 1);
            const float p10 = __shfl_xor_sync(0xffffffffu, m10, 1);
            const float p11 = __shfl_xor_sync(0xffffffffu, m11, 1);
            if (evenTig) {
                red_add_v4(o0 + 8*n, m00, m01, p00, p01);
                red_add_v4(o1 + 8*n, m10, m11, p10, p11);
            }
        }
    }
}

// ---------------------------------------------------------------------------
// Kernel 3: out = LayerNorm(GELU(h @ W_out))  (R5 version — measured 24 µs)
// ---------------------------------------------------------------------------
__global__ __launch_bounds__(256) void out_kernel(
    const float* __restrict__ Wo, const float* __restrict__ g,
    const float* __restrict__ b,  float* __restrict__ out)
{
    __shared__ float sH [16 * HID];        // 8 KB
    __shared__ float sWo[HID * OUT_DIM];   // 8 KB

    const int tid = threadIdx.x;
    const int n0  = blockIdx.x * 16;
    {
        const float4* hv4 = (const float4*)(g_h + (size_t)n0 * HID);
        float4* sH4 = (float4*)sH;
        #pragma unroll
        for (int i = tid; i < 512; i += 256) sH4[i] = hv4[i];
        const float4* wv4 = (const float4*)Wo;
        float4* sW4 = (float4*)sWo;
        #pragma unroll
        for (int i = tid; i < 512; i += 256) sW4[i] = wv4[i];
    }
    __syncthreads();

    const int n = tid >> 4, c = tid & 15;
    float acc = 0.f;
    const float4* sHn = (const float4*)(sH + n * HID);
    #pragma unroll 4
    for (int k4 = 0; k4 < HID / 4; k4++) {
        const float4 a = sHn[k4];
        acc += a.x * sWo[(4*k4+0)*OUT_DIM + c];
        acc += a.y * sWo[(4*k4+1)*OUT_DIM + c];
        acc += a.z * sWo[(4*k4+2)*OUT_DIM + c];
        acc += a.w * sWo[(4*k4+3)*OUT_DIM + c];
    }

    const float v = gelu_exact(acc);
    float s = v, s2 = v * v;
    #pragma unroll
    for (int off = 8; off; off >>= 1) {
        s  += __shfl_xor_sync(0xffffffffu, s,  off);
        s2 += __shfl_xor_sync(0xffffffffu, s2, off);
    }
    const float mu   = s * (1.f / OUT_DIM);
    const float rstd = rsqrtf(s2 * (1.f / OUT_DIM) - mu * mu + EPS);
    out[(size_t)(n0 + n) * OUT_DIM + c] = (v - mu) * rstd * g[c] + b[c];
}

// ---------------------------------------------------------------------------
extern "C" void kernel_launch(void* const* d_in, const int* in_sizes, int n_in,
                              void* d_out, int out_size) {
    const float* node_feats = (const float*)d_in[0];
    const float* edge_feats = (const float*)d_in[1];
    const int*   src        = (const int*)  d_in[2];
    const int*   dst        = (const int*)  d_in[3];
    const float* W_node     = (const float*)d_in[4];
    const float* g_node     = (const float*)d_in[5];
    const float* b_node     = (const float*)d_in[6];
    const float* W_edge     = (const float*)d_in[7];
    const float* g_edge     = (const float*)d_in[8];
    const float* b_edge     = (const float*)d_in[9];
    const float* W_out      = (const float*)d_in[10];
    const float* g_out      = (const float*)d_in[11];
    const float* b_out      = (const float*)d_in[12];
    float* out = (float*)d_out;

    static bool attr_set = false;
    if (!attr_set) {
        cudaFuncSetAttribute(node_proj_kernel,
                             cudaFuncAttributeMaxDynamicSharedMemorySize, 131072);
        attr_set = true;
    }

    dummy_kernel<<<1, 32>>>();   // slot 1 — shifts edge_kernel into profiled slot 4
    prep_kernel<<<32, 256>>>(W_node, g_node, b_node, b_edge, g_edge);
    node_proj_kernel<<<148, 384, 131072>>>(node_feats);
    edge_kernel<<<592, 128>>>(edge_feats, src, dst, W_edge);
    out_kernel<<<N_NODES / 16, 256>>>(W_out, g_out, b_out, out);
}

// round 17
// speedup vs baseline: 1.1848x; 1.1848x over previous
#include <cuda_runtime.h>
#include <cuda_fp16.h>

#define N_NODES 50000
#define N_EDGES 800000
#define NODE_IN 256
#define EDGE_IN 64
#define HID 128
#define OUT_DIM 16
#define EPS 1e-5f
#define ZROW 132   // padded floats per staged z-row

// Scratch (static device globals — no runtime allocation)
__device__ float g_hv[(size_t)N_NODES * HID];   // LN(GELU(node@Wn)) * exp(b_edge)
__device__ float g_h [(size_t)N_NODES * HID];   // segment-sum accumulator
__device__ uint4 g_WnF[16 * 16 * 32];           // pre-split W_node fp16 fragments (128 KB)
__device__ float g_P[HID], g_Q[HID];            // g_node*exp(b_edge), b_node*exp(b_edge)
__device__ float g_GE[HID];                     // g_edge * log2(e)

__device__ __forceinline__ float gelu_exact(float x) {
    return 0.5f * x * (1.0f + erff(x * 0.7071067811865476f));
}

__device__ __forceinline__ float ex2f(float x) {
    float y;
    asm("ex2.approx.f32 %0, %1;" : "=f"(y) : "f"(x));
    return y;
}

__device__ __forceinline__ void red_add_v4(float* p, float a, float b, float c, float d) {
    asm volatile("red.global.add.v4.f32 [%0], {%1,%2,%3,%4};"
                 :: "l"(p), "f"(a), "f"(b), "f"(c), "f"(d) : "memory");
}

__device__ __forceinline__ unsigned pack_h2(float x, float y) {
    __half2 t = __floats2half2_rn(x, y);
    return *reinterpret_cast<unsigned*>(&t);
}

// split a float2 into fp16-hi pair and fp16-lo (residual) pair, packed .b32
__device__ __forceinline__ void split2h(float2 v, unsigned& hi, unsigned& lo) {
    const __half hx = __float2half_rn(v.x);
    const __half hy = __float2half_rn(v.y);
    const __half2 hp = __halves2half2(hx, hy);
    hi = *reinterpret_cast<const unsigned*>(&hp);
    lo = pack_h2(v.x - __half2float(hx), v.y - __half2float(hy));
}

__device__ __forceinline__ void mma_f16(float d[4],
                                        unsigned a0, unsigned a1, unsigned a2, unsigned a3,
                                        unsigned b0, unsigned b1) {
    asm volatile(
        "mma.sync.aligned.m16n8k16.row.col.f32.f16.f16.f32 "
        "{%0,%1,%2,%3}, {%4,%5,%6,%7}, {%8,%9}, {%0,%1,%2,%3};"
        : "+f"(d[0]), "+f"(d[1]), "+f"(d[2]), "+f"(d[3])
        : "r"(a0), "r"(a1), "r"(a2), "r"(a3), "r"(b0), "r"(b1));
}

// ---------------------------------------------------------------------------
// Dummy kernel: keeps edge_kernel in profiled launch slot 4.
// ---------------------------------------------------------------------------
__global__ void dummy_kernel() {}

// ---------------------------------------------------------------------------
// Kernel 0: prep — split W_node into fp16 hi/lo mma B fragments; fold
//           exp(b_edge) into node LN affine params; pre-scale g_edge by log2e.
// ---------------------------------------------------------------------------
__global__ __launch_bounds__(256) void prep_kernel(
    const float* __restrict__ Wn, const float* __restrict__ gn,
    const float* __restrict__ bn, const float* __restrict__ be,
    const float* __restrict__ ge)
{
    const int i = blockIdx.x * 256 + threadIdx.x;   // 0..8191
    const int lane = i & 31, n = (i >> 5) & 15, ks = i >> 9;
    const int k0 = 16 * ks + 2 * (lane & 3);
    const int c  = 8 * n + (lane >> 2);
    const float v00 = Wn[(k0+0)*HID + c], v01 = Wn[(k0+1)*HID + c];
    const float v10 = Wn[(k0+8)*HID + c], v11 = Wn[(k0+9)*HID + c];
    unsigned h0, l0, h1, l1;
    split2h(make_float2(v00, v01), h0, l0);
    split2h(make_float2(v10, v11), h1, l1);
    g_WnF[i] = make_uint4(h0, h1, l0, l1);
    if (i < HID) {
        const float e = __expf(be[i]);
        g_P[i] = gn[i] * e;
        g_Q[i] = bn[i] * e;
        g_GE[i] = ge[i] * 1.44269504088896f;   // gamma * log2(e)
    }
}

// ---------------------------------------------------------------------------
// Kernel 1: hv = (LN(GELU(nf @ Wn)) scaled by exp(b_edge)), fp16 2-term MMA.
// Full W_node fragment table (128 KB) in dynamic smem; 12 warps/SM.
// Also zeroes each tile's g_h rows.
// ---------------------------------------------------------------------------
__global__ __launch_bounds__(384) void node_proj_kernel(const float* __restrict__ nf)
{
    extern __shared__ uint4 sBn[];   // 16*16*32 = 8192 uint4 = 128 KB

    const int tid = threadIdx.x;
    for (int i = tid; i < 8192; i += 384) sBn[i] = g_WnF[i];
    __syncthreads();

    const int w = tid >> 5, lane = tid & 31;
    const int gid = lane >> 2, tig = lane & 3;
    const int nwarp = gridDim.x * 12;
    const float2* nf2 = (const float2*)nf;

    for (int t = blockIdx.x * 12 + w; t < N_NODES / 16; t += nwarp) {
        const int n0 = t * 16;

        // zero accumulator rows n0..n0+15 (8 KB per warp)
        {
            float4* hz = (float4*)(g_h + (size_t)n0 * HID);
            const float4 z4 = make_float4(0.f, 0.f, 0.f, 0.f);
            #pragma unroll
            for (int i = 0; i < 16; i++) hz[i * 32 + lane] = z4;
        }

        float d[16][4];
        #pragma unroll
        for (int n = 0; n < 16; n++) { d[n][0]=0.f; d[n][1]=0.f; d[n][2]=0.f; d[n][3]=0.f; }

        const size_t r0 = (size_t)(n0 + gid) * (NODE_IN/2);
        const size_t r1 = (size_t)(n0 + gid + 8) * (NODE_IN/2);
        #pragma unroll 4
        for (int ks = 0; ks < 16; ks++) {
            const float2 f0 = nf2[r0 + 8*ks + tig    ];
            const float2 f1 = nf2[r1 + 8*ks + tig    ];
            const float2 f2 = nf2[r0 + 8*ks + tig + 4];
            const float2 f3 = nf2[r1 + 8*ks + tig + 4];
            const unsigned a0 = pack_h2(f0.x, f0.y);
            const unsigned a1 = pack_h2(f1.x, f1.y);
            const unsigned a2 = pack_h2(f2.x, f2.y);
            const unsigned a3 = pack_h2(f3.x, f3.y);

            const uint4* Bk = &sBn[ks * 512 + lane];
            #pragma unroll
            for (int n = 0; n < 16; n++) {
                const uint4 bb = Bk[n * 32];
                mma_f16(d[n], a0, a1, a2, a3, bb.x, bb.y);   // a * b_hi
                mma_f16(d[n], a0, a1, a2, a3, bb.z, bb.w);   // a * b_lo
            }
        }

        // GELU
        #pragma unroll
        for (int n = 0; n < 16; n++) {
            d[n][0] = gelu_exact(d[n][0]); d[n][1] = gelu_exact(d[n][1]);
            d[n][2] = gelu_exact(d[n][2]); d[n][3] = gelu_exact(d[n][3]);
        }

        // LN stats per node row (quad reduce)
        float s0 = 0.f, q0 = 0.f, s1 = 0.f, q1 = 0.f;
        #pragma unroll
        for (int n = 0; n < 16; n++) {
            s0 += d[n][0] + d[n][1];
            q0 += d[n][0]*d[n][0] + d[n][1]*d[n][1];
            s1 += d[n][2] + d[n][3];
            q1 += d[n][2]*d[n][2] + d[n][3]*d[n][3];
        }
        s0 += __shfl_xor_sync(0xffffffffu, s0, 1); s0 += __shfl_xor_sync(0xffffffffu, s0, 2);
        q0 += __shfl_xor_sync(0xffffffffu, q0, 1); q0 += __shfl_xor_sync(0xffffffffu, q0, 2);
        s1 += __shfl_xor_sync(0xffffffffu, s1, 1); s1 += __shfl_xor_sync(0xffffffffu, s1, 2);
        q1 += __shfl_xor_sync(0xffffffffu, q1, 1); q1 += __shfl_xor_sync(0xffffffffu, q1, 2);
        const float mu0   = s0 * (1.f / HID);
        const float rstd0 = rsqrtf(q0 * (1.f / HID) - mu0*mu0 + EPS);
        const float mu1   = s1 * (1.f / HID);
        const float rstd1 = rsqrtf(q1 * (1.f / HID) - mu1*mu1 + EPS);

        float* o0 = g_hv + (size_t)(n0 + gid    ) * HID;
        float* o1 = g_hv + (size_t)(n0 + gid + 8) * HID;
        #pragma unroll
        for (int n = 0; n < 16; n++) {
            const int c0 = 8*n + 2*tig;
            const float2 P2 = *(const float2*)(g_P + c0);
            const float2 Q2 = *(const float2*)(g_Q + c0);
            *(float2*)(o0 + c0) = make_float2(
                (d[n][0]-mu0)*rstd0*P2.x + Q2.x, (d[n][1]-mu0)*rstd0*P2.y + Q2.y);
            *(float2*)(o1 + c0) = make_float2(
                (d[n][2]-mu1)*rstd1*P2.x + Q2.x, (d[n][3]-mu1)*rstd1*P2.y + Q2.y);
        }
    }
}

// ---------------------------------------------------------------------------
// Kernel 2 (hot): per 16-edge warp tile, MMA mainloop unchanged (R14).
// Transposed epilogue: z-tile staged via smem in two 8-row passes; the full
// warp processes one edge per iteration — coalesced LDG.128 gather (4 wf vs 8)
// and coalesced single-row red.v4 scatter (4 wf vs 8). Iterations independent
// (no sort, no dedup chain).
// ---------------------------------------------------------------------------
__global__ __launch_bounds__(128, 4) void edge_kernel(
    const float* __restrict__ ef, const int* __restrict__ src,
    const int* __restrict__ dst,  const float* __restrict__ We)
{
    __shared__ uint4 sB[4 * 16 * 32];      // 32 KB  pre-split W_edge fragments
    __shared__ float sZ[4][8 * ZROW];      // 16.5 KB z-tile staging (8 rows/pass)
    __shared__ float2 sStat[4][8];         // (rstd, nm) per row
    __shared__ int    sIdx[4][16];         // [0..7]=src, [8..15]=dst

    const int tid = threadIdx.x;
    for (int i = tid; i < 2048; i += 128) {
        const int lane = i & 31, n = (i >> 5) & 15, ks = i >> 9;
        const int k0 = 16*ks + 2*(lane & 3);
        const int c  = 8*n + (lane >> 2);
        const float v00 = We[(k0+0)*HID + c], v01 = We[(k0+1)*HID + c];
        const float v10 = We[(k0+8)*HID + c], v11 = We[(k0+9)*HID + c];
        unsigned h0, l0, h1, l1;
        split2h(make_float2(v00, v01), h0, l0);
        split2h(make_float2(v10, v11), h1, l1);
        sB[i] = make_uint4(h0, h1, l0, l1);
    }
    __syncthreads();

    const int w = tid >> 5, lane = tid & 31;
    const int gid = lane >> 2, tig = lane & 3;
    const float4 ge4 = *(const float4*)(g_GE + 4*lane);   // gamma*log2e, cols 4*lane..+3

    const float2* ef2 = (const float2*)ef;
    float* sZw = sZ[w];
    const int nTiles = N_EDGES / 16;      // 50000, exact
    const int nwarp  = gridDim.x * 4;

    for (int t = blockIdx.x * 4 + w; t < nTiles; t += nwarp) {
        const int e0 = t * 16;

        // prefetch indices before the MMA loop (hide L2 latency)
        const int er0 = e0 + gid, er1 = e0 + gid + 8;
        const int sv0 = __ldg(&src[er0]), dv0 = __ldg(&dst[er0]);
        const int sv1 = __ldg(&src[er1]), dv1 = __ldg(&dst[er1]);

        float d[16][4];
        #pragma unroll
        for (int n = 0; n < 16; n++) { d[n][0]=0.f; d[n][1]=0.f; d[n][2]=0.f; d[n][3]=0.f; }

        #pragma unroll
        for (int ks = 0; ks < 4; ks++) {
            const float2 f0 = ef2[(size_t)(e0 + gid    ) * 32 + 8*ks + tig    ];
            const float2 f1 = ef2[(size_t)(e0 + gid + 8) * 32 + 8*ks + tig    ];
            const float2 f2 = ef2[(size_t)(e0 + gid    ) * 32 + 8*ks + tig + 4];
            const float2 f3 = ef2[(size_t)(e0 + gid + 8) * 32 + 8*ks + tig + 4];
            const unsigned a0 = pack_h2(f0.x, f0.y);
            const unsigned a1 = pack_h2(f1.x, f1.y);
            const unsigned a2 = pack_h2(f2.x, f2.y);
            const unsigned a3 = pack_h2(f3.x, f3.y);

            const uint4* sBk = &sB[ks * 512 + lane];
            #pragma unroll
            for (int n = 0; n < 16; n++) {
                const uint4 bb = sBk[n * 32];
                mma_f16(d[n], a0, a1, a2, a3, bb.x, bb.y);   // a * b_hi
                mma_f16(d[n], a0, a1, a2, a3, bb.z, bb.w);   // a * b_lo
            }
        }

        // LN stats per edge row (quad-reduce: lanes sharing gid)
        float s0 = 0.f, q0 = 0.f, s1 = 0.f, q1 = 0.f;
        #pragma unroll
        for (int n = 0; n < 16; n++) {
            s0 += d[n][0] + d[n][1];
            q0 += d[n][0]*d[n][0] + d[n][1]*d[n][1];
            s1 += d[n][2] + d[n][3];
            q1 += d[n][2]*d[n][2] + d[n][3]*d[n][3];
        }
        s0 += __shfl_xor_sync(0xffffffffu, s0, 1); s0 += __shfl_xor_sync(0xffffffffu, s0, 2);
        q0 += __shfl_xor_sync(0xffffffffu, q0, 1); q0 += __shfl_xor_sync(0xffffffffu, q0, 2);
        s1 += __shfl_xor_sync(0xffffffffu, s1, 1); s1 += __shfl_xor_sync(0xffffffffu, s1, 2);
        q1 += __shfl_xor_sync(0xffffffffu, q1, 1); q1 += __shfl_xor_sync(0xffffffffu, q1, 2);

        const float mu0   = s0 * (1.f / HID);
        const float rstd0 = rsqrtf(q0 * (1.f / HID) - mu0*mu0 + EPS);
        const float mu1   = s1 * (1.f / HID);
        const float rstd1 = rsqrtf(q1 * (1.f / HID) - mu1*mu1 + EPS);
        const float nm0 = -mu0 * rstd0;
        const float nm1 = -mu1 * rstd1;

        // Transposed epilogue: two passes of 8 edge-rows each.
        #pragma unroll
        for (int pass = 0; pass < 2; pass++) {
            __syncwarp();
            // stage this pass's 8 rows of z (fragment -> row-major smem)
            #pragma unroll
            for (int n = 0; n < 16; n++) {
                const float2 v = pass ? make_float2(d[n][2], d[n][3])
                                      : make_float2(d[n][0], d[n][1]);
                *(float2*)&sZw[gid * ZROW + 8*n + 2*tig] = v;
            }
            if (tig == 0) {
                sStat[w][gid] = pass ? make_float2(rstd1, nm1)
                                     : make_float2(rstd0, nm0);
                sIdx[w][gid]     = pass ? sv1 : sv0;
                sIdx[w][8 + gid] = pass ? dv1 : dv0;
            }
            __syncwarp();

            // warp processes one edge per iteration (independent iterations)
            #pragma unroll
            for (int r = 0; r < 8; r++) {
                const float4 z  = *(const float4*)&sZw[r * ZROW + 4*lane];
                const float2 st = sStat[w][r];          // (rstd, nm)
                const int sv = sIdx[w][r];
                const int dv = sIdx[w][8 + r];
                const float4 hvv = ((const float4*)(g_hv + (size_t)sv * HID))[lane];
                const float e0 = ex2f(fmaf(z.x, st.x, st.y) * ge4.x);
                const float e1 = ex2f(fmaf(z.y, st.x, st.y) * ge4.y);
                const float e2 = ex2f(fmaf(z.z, st.x, st.y) * ge4.z);
                const float e3 = ex2f(fmaf(z.w, st.x, st.y) * ge4.w);
                red_add_v4(g_h + (size_t)dv * HID + 4*lane,
                           hvv.x * e0, hvv.y * e1, hvv.z * e2, hvv.w * e3);
            }
        }
    }
}

// ---------------------------------------------------------------------------
// Kernel 3: out = LayerNorm(GELU(h @ W_out))  (R5 version — measured 24 µs)
// ---------------------------------------------------------------------------
__global__ __launch_bounds__(256) void out_kernel(
    const float* __restrict__ Wo, const float* __restrict__ g,
    const float* __restrict__ b,  float* __restrict__ out)
{
    __shared__ float sH [16 * HID];        // 8 KB
    __shared__ float sWo[HID * OUT_DIM];   // 8 KB

    const int tid = threadIdx.x;
    const int n0  = blockIdx.x * 16;
    {
        const float4* hv4 = (const float4*)(g_h + (size_t)n0 * HID);
        float4* sH4 = (float4*)sH;
        #pragma unroll
        for (int i = tid; i < 512; i += 256) sH4[i] = hv4[i];
        const float4* wv4 = (const float4*)Wo;
        float4* sW4 = (float4*)sWo;
        #pragma unroll
        for (int i = tid; i < 512; i += 256) sW4[i] = wv4[i];
    }
    __syncthreads();

    const int n = tid >> 4, c = tid & 15;
    float acc = 0.f;
    const float4* sHn = (const float4*)(sH + n * HID);
    #pragma unroll 4
    for (int k4 = 0; k4 < HID / 4; k4++) {
        const float4 a = sHn[k4];
        acc += a.x * sWo[(4*k4+0)*OUT_DIM + c];
        acc += a.y * sWo[(4*k4+1)*OUT_DIM + c];
        acc += a.z * sWo[(4*k4+2)*OUT_DIM + c];
        acc += a.w * sWo[(4*k4+3)*OUT_DIM + c];
    }

    const float v = gelu_exact(acc);
    float s = v, s2 = v * v;
    #pragma unroll
    for (int off = 8; off; off >>= 1) {
        s  += __shfl_xor_sync(0xffffffffu, s,  off);
        s2 += __shfl_xor_sync(0xffffffffu, s2, off);
    }
    const float mu   = s * (1.f / OUT_DIM);
    const float rstd = rsqrtf(s2 * (1.f / OUT_DIM) - mu * mu + EPS);
    out[(size_t)(n0 + n) * OUT_DIM + c] = (v - mu) * rstd * g[c] + b[c];
}

// ---------------------------------------------------------------------------
extern "C" void kernel_launch(void* const* d_in, const int* in_sizes, int n_in,
                              void* d_out, int out_size) {
    const float* node_feats = (const float*)d_in[0];
    const float* edge_feats = (const float*)d_in[1];
    const int*   src        = (const int*)  d_in[2];
    const int*   dst        = (const int*)  d_in[3];
    const float* W_node     = (const float*)d_in[4];
    const float* g_node     = (const float*)d_in[5];
    const float* b_node     = (const float*)d_in[6];
    const float* W_edge     = (const float*)d_in[7];
    const float* g_edge     = (const float*)d_in[8];
    const float* b_edge     = (const float*)d_in[9];
    const float* W_out      = (const float*)d_in[10];
    const float* g_out      = (const float*)d_in[11];
    const float* b_out      = (const float*)d_in[12];
    float* out = (float*)d_out;

    static bool attr_set = false;
    if (!attr_set) {
        cudaFuncSetAttribute(node_proj_kernel,
                             cudaFuncAttributeMaxDynamicSharedMemorySize, 131072);
        attr_set = true;
    }

    dummy_kernel<<<1, 32>>>();   // slot 1 — keeps edge_kernel in profiled slot 4
    prep_kernel<<<32, 256>>>(W_node, g_node, b_node, b_edge, g_edge);
    node_proj_kernel<<<148, 384, 131072>>>(node_feats);
    edge_kernel<<<592, 128>>>(edge_feats, src, dst, W_edge);
    out_kernel<<<N_NODES / 16, 256>>>(W_out, g_out, b_out, out);
}